// round 15
// baseline (speedup 1.0000x reference)
#include <cuda_runtime.h>

// StructuredPruningIF: integrate-and-fire over T=4 timesteps.
//   mem = 0.5*thre; for t in 0..3: mem += x[t]; spike = (mem>=thre)?thre:0; mem -= spike
// Pure streaming: 256MB read + 256MB write, irreducible traffic. HBM-bound.
//
// FINAL: flat one-shot launch, one float4 lane/thread, front-batched MLP=4
// timestep loads, plain loads/stores, 32 regs, block=128, grid=32768.
// Sustains 6.4-6.5 TB/s (81-82% of 8 TB/s spec) = the empirical HBM ceiling
// for a balanced 50/50 read/write stream on GB300. dur 81.95-82.02us across
// seven confirmation runs (0.07us spread); kernel 74.3-75.1us.
//
// Full experiment ledger (GB300 sm_103a, 14 rounds, 17 measurements):
//   R1 plain flat b256:        74.6us kernel / 82.0us dur, 6.49 TB/s
//   R2 __ldcs/__stcs + MLP8:   75.4us neutral, occ 79->49% (48 regs)
//   R3 persistent grid-stride: 80.7us REGRESSED — loop-carried loads behind
//      stores -> sustained-MLP drop (6.0 TB/s). Flat + front-batched wins.
//   R4 __stcs stores:          75.8us neutral
//   R5 plain b256:             75.4us, 6.43 TB/s
//   R6 __stwt stores:          74.3us, 6.52 TB/s (noise)
//   R7 plain b256:             75.2us, 6.44 TB/s
//   R8 plain b128:             74.4us / 81.98us dur, 6.52 TB/s   <- FINAL
//   R9 plain b128:             75.0us / 81.95us dur, 6.46 TB/s
//   R10 plain b128:            75.1us / 82.02us dur, 6.45 TB/s
//   R11 plain b128:            74.7us / 82.02us dur, 6.48 TB/s
//   R12 plain b128:            74.3us / 82.02us dur, 6.53 TB/s, DRAM 82.4%
//   R13 plain b128:            74.5us / 82.02us dur, 6.50 TB/s
//   R14 plain b128:            74.8us / 81.98us dur, 6.48 TB/s
// Swept: cache policy x4, MLP depth x2, launch structure x2, block size x2.
// sm_103a has no 256-bit STG (vector width maxed); TMA hits the same LTS
// cap (path-independent); compute pipes <10%, issue 14%, L2 pass-through.
// Residual gap to spec is DRAM R/W bus-turnaround — not software-addressable.

#define T_STEPS 4

__global__ __launch_bounds__(128) void if_kernel(
    const float4* __restrict__ x,
    const float* __restrict__ thresh,
    float4* __restrict__ out,
    int n4)          // spatial float4 count per timestep (== timestep stride)
{
    int i = blockIdx.x * blockDim.x + threadIdx.x;
    if (i >= n4) return;

    const float thre = __ldg(thresh);
    const long s = n4;

    // Front-batched independent loads (MLP=4), first in program order so
    // every CTA fills the L1tex queue immediately at launch.
    float4 x0 = x[0 * s + i];
    float4 x1 = x[1 * s + i];
    float4 x2 = x[2 * s + i];
    float4 x3 = x[3 * s + i];

    float4 xts[T_STEPS] = {x0, x1, x2, x3};
    const float half_thre = 0.5f * thre;
    float4 mem = make_float4(half_thre, half_thre, half_thre, half_thre);

#pragma unroll
    for (int t = 0; t < T_STEPS; t++) {
        float4 xt = xts[t];
        float4 spike;

        mem.x += xt.x; spike.x = (mem.x >= thre) ? thre : 0.0f; mem.x -= spike.x;
        mem.y += xt.y; spike.y = (mem.y >= thre) ? thre : 0.0f; mem.y -= spike.y;
        mem.z += xt.z; spike.z = (mem.z >= thre) ? thre : 0.0f; mem.z -= spike.z;
        mem.w += xt.w; spike.w = (mem.w >= thre) ? thre : 0.0f; mem.w -= spike.w;

        out[t * s + i] = spike;
    }
}

extern "C" void kernel_launch(void* const* d_in, const int* in_sizes, int n_in,
                              void* d_out, int out_size) {
    const float* x      = (const float*)d_in[0];   // [512,128,32,32] fp32
    const float* thresh = (const float*)d_in[1];   // [1] fp32
    float* out          = (float*)d_out;

    int total = in_sizes[0];            // 67,108,864
    int per_t = total / T_STEPS;        // 16,777,216
    int n4 = per_t / 4;                 // 4,194,304 float4 lanes

    int threads = 128;
    int blocks = (n4 + threads - 1) / threads;   // 32768
    if_kernel<<<blocks, threads>>>((const float4*)x, thresh, (float4*)out, n4);
}

// round 16
// speedup vs baseline: 1.0012x; 1.0012x over previous
#include <cuda_runtime.h>

// StructuredPruningIF: integrate-and-fire over T=4 timesteps.
//   mem = 0.5*thre; for t in 0..3: mem += x[t]; spike = (mem>=thre)?thre:0; mem -= spike
// Pure streaming: 256MB read + 256MB write, irreducible traffic. HBM-bound.
//
// FINAL: flat one-shot launch, one float4 lane/thread, front-batched MLP=4
// timestep loads, plain loads/stores, 32 regs, block=128, grid=32768.
// Sustains 6.4-6.5 TB/s (81-82% of 8 TB/s spec) = the empirical HBM ceiling
// for a balanced 50/50 read/write stream on GB300. dur 81.95-82.05us across
// eight confirmation runs; kernel 74.3-75.3us.
//
// Full experiment ledger (GB300 sm_103a, 15 rounds, 18 measurements):
//   R1 plain flat b256:        74.6us kernel / 82.0us dur, 6.49 TB/s
//   R2 __ldcs/__stcs + MLP8:   75.4us neutral, occ 79->49% (48 regs)
//   R3 persistent grid-stride: 80.7us REGRESSED — loop-carried loads behind
//      stores -> sustained-MLP drop (6.0 TB/s). Flat + front-batched wins.
//   R4 __stcs stores:          75.8us neutral
//   R5 plain b256:             75.4us, 6.43 TB/s
//   R6 __stwt stores:          74.3us, 6.52 TB/s (noise)
//   R7 plain b256:             75.2us, 6.44 TB/s
//   R8 plain b128:             74.4us / 81.98us dur, 6.52 TB/s   <- FINAL
//   R9 plain b128:             75.0us / 81.95us dur, 6.46 TB/s
//   R10 plain b128:            75.1us / 82.02us dur, 6.45 TB/s
//   R11 plain b128:            74.7us / 82.02us dur, 6.48 TB/s
//   R12 plain b128:            74.3us / 82.02us dur, 6.53 TB/s, DRAM 82.4%
//   R13 plain b128:            74.5us / 82.02us dur, 6.50 TB/s
//   R14 plain b128:            74.8us / 81.98us dur, 6.48 TB/s
//   R15 plain b128:            75.3us / 82.05us dur, 6.44 TB/s
// Swept: cache policy x4, MLP depth x2, launch structure x2, block size x2.
// sm_103a has no 256-bit STG (vector width maxed); TMA hits the same LTS
// cap (path-independent); compute pipes <10%, issue 14%, L2 pass-through.
// Residual gap to spec is DRAM R/W bus-turnaround — not software-addressable.

#define T_STEPS 4

__global__ __launch_bounds__(128) void if_kernel(
    const float4* __restrict__ x,
    const float* __restrict__ thresh,
    float4* __restrict__ out,
    int n4)          // spatial float4 count per timestep (== timestep stride)
{
    int i = blockIdx.x * blockDim.x + threadIdx.x;
    if (i >= n4) return;

    const float thre = __ldg(thresh);
    const long s = n4;

    // Front-batched independent loads (MLP=4), first in program order so
    // every CTA fills the L1tex queue immediately at launch.
    float4 x0 = x[0 * s + i];
    float4 x1 = x[1 * s + i];
    float4 x2 = x[2 * s + i];
    float4 x3 = x[3 * s + i];

    float4 xts[T_STEPS] = {x0, x1, x2, x3};
    const float half_thre = 0.5f * thre;
    float4 mem = make_float4(half_thre, half_thre, half_thre, half_thre);

#pragma unroll
    for (int t = 0; t < T_STEPS; t++) {
        float4 xt = xts[t];
        float4 spike;

        mem.x += xt.x; spike.x = (mem.x >= thre) ? thre : 0.0f; mem.x -= spike.x;
        mem.y += xt.y; spike.y = (mem.y >= thre) ? thre : 0.0f; mem.y -= spike.y;
        mem.z += xt.z; spike.z = (mem.z >= thre) ? thre : 0.0f; mem.z -= spike.z;
        mem.w += xt.w; spike.w = (mem.w >= thre) ? thre : 0.0f; mem.w -= spike.w;

        out[t * s + i] = spike;
    }
}

extern "C" void kernel_launch(void* const* d_in, const int* in_sizes, int n_in,
                              void* d_out, int out_size) {
    const float* x      = (const float*)d_in[0];   // [512,128,32,32] fp32
    const float* thresh = (const float*)d_in[1];   // [1] fp32
    float* out          = (float*)d_out;

    int total = in_sizes[0];            // 67,108,864
    int per_t = total / T_STEPS;        // 16,777,216
    int n4 = per_t / 4;                 // 4,194,304 float4 lanes

    int threads = 128;
    int blocks = (n4 + threads - 1) / threads;   // 32768
    if_kernel<<<blocks, threads>>>((const float4*)x, thresh, (float4*)out, n4);
}